// round 10
// baseline (speedup 1.0000x reference)
#include <cuda_runtime.h>
#include <cuda_fp16.h>
#include <cstdint>

// ---------------------------------------------------------------------------
// Florence2 window attention — all matmuls on mma.sync (fp16 in, fp32 acc).
// R10: hgemm inner loop software-pipelines ldmatrix fragments (A one s-step
// ahead, B one j2 ahead) so the tensor pipe never drains at step boundaries.
// ---------------------------------------------------------------------------

#define NWIN   128
#define NTOK   144
#define DIM    512
#define NHEAD  16
#define HDIM   32
#define MTOT   (NWIN * NTOK)     // 18432
#define NQKV   1536

#define SROW   72                // hgemm smem row stride in halves (144B)

// ---------------- scratch (device globals; device-code refs only) ----------
__device__ __align__(16) __half g_x  [MTOT * DIM];
__device__ __align__(16) __half g_wq [NQKV * DIM];
__device__ __align__(16) __half g_wp [DIM * DIM];
__device__ __align__(16) __half g_qh [NWIN * NHEAD * NTOK * HDIM];
__device__ __align__(16) __half g_kh [NWIN * NHEAD * NTOK * HDIM];
__device__ __align__(16) __half g_vT [NWIN * NHEAD * HDIM * NTOK];
__device__ __align__(16) __half g_ao [MTOT * DIM];

// ---------------- PTX helpers ----------------------------------------------
__device__ __forceinline__ uint32_t smem_u32(const void* p) {
    uint32_t a;
    asm("{ .reg .u64 t; cvta.to.shared.u64 t, %1; cvt.u32.u64 %0, t; }" : "=r"(a) : "l"(p));
    return a;
}
__device__ __forceinline__ void cp_async16(uint32_t s, const void* g) {
    asm volatile("cp.async.cg.shared.global [%0], [%1], 16;" :: "r"(s), "l"(g));
}
__device__ __forceinline__ void cp_commit() { asm volatile("cp.async.commit_group;"); }
__device__ __forceinline__ void cp_wait0()  { asm volatile("cp.async.wait_group 0;"); }

__device__ __forceinline__ void ldsm_x4(uint32_t* r, uint32_t addr) {
    asm volatile("ldmatrix.sync.aligned.m8n8.x4.shared.b16 {%0,%1,%2,%3}, [%4];"
        : "=r"(r[0]), "=r"(r[1]), "=r"(r[2]), "=r"(r[3]) : "r"(addr));
}
__device__ __forceinline__ void mma16816(float* d, const uint32_t* a,
                                         uint32_t b0, uint32_t b1) {
    asm volatile("mma.sync.aligned.m16n8k16.row.col.f32.f16.f16.f32 "
        "{%0,%1,%2,%3}, {%4,%5,%6,%7}, {%8,%9}, {%0,%1,%2,%3};"
        : "+f"(d[0]), "+f"(d[1]), "+f"(d[2]), "+f"(d[3])
        : "r"(a[0]), "r"(a[1]), "r"(a[2]), "r"(a[3]), "r"(b0), "r"(b1));
}

__device__ __forceinline__ int hidden_row_off(int m) {
    int win = m / NTOK, t = m % NTOK;
    int b = win >> 4, yw = (win >> 2) & 3, xw = win & 3;
    int y = yw * 12 + t / 12;
    int x = xw * 12 + t % 12;
    return ((b * 48 + y) * 48 + x) * DIM;
}

// ---------------------------------------------------------------------------
// conversion kernels (fp32 -> fp16)
// ---------------------------------------------------------------------------
__global__ void convert_x_kernel(const float* __restrict__ hidden) {
    int idx = blockIdx.x * 256 + threadIdx.x;
    int m = idx >> 6, seg = idx & 63;
    const float* src = hidden + hidden_row_off(m) + seg * 8;
    float4 f0 = *(const float4*)src;
    float4 f1 = *(const float4*)(src + 4);
    __align__(16) __half h[8];
    h[0] = __float2half(f0.x); h[1] = __float2half(f0.y);
    h[2] = __float2half(f0.z); h[3] = __float2half(f0.w);
    h[4] = __float2half(f1.x); h[5] = __float2half(f1.y);
    h[6] = __float2half(f1.z); h[7] = __float2half(f1.w);
    *(uint4*)&g_x[m * DIM + seg * 8] = *(uint4*)h;
}

// both weight transposes in ONE launch: x-blocks [0,48) -> qkv, [48,64) -> proj
__global__ void convert_w_kernel(const float* __restrict__ Wq,
                                 const float* __restrict__ Wp) {
    __shared__ float t[32][33];
    const int bx = blockIdx.x;
    const bool isP = bx >= (NQKV / 32);
    const float* __restrict__ W = isP ? Wp : Wq;
    const int N = isP ? DIM : NQKV;
    __half* __restrict__ outT = isP ? g_wp : g_wq;
    const int n0 = (isP ? bx - NQKV / 32 : bx) * 32;
    const int k0 = blockIdx.y * 32;
    int tx = threadIdx.x, ty = threadIdx.y;
    #pragma unroll
    for (int j = 0; j < 4; ++j)
        t[ty + 8 * j][tx] = W[(k0 + ty + 8 * j) * N + n0 + tx];
    __syncthreads();
    #pragma unroll
    for (int j = 0; j < 4; ++j)
        outT[(n0 + ty + 8 * j) * DIM + k0 + tx] = __float2half(t[tx][ty + 8 * j]);
}

// ---------------------------------------------------------------------------
// HGEMM mainloop: 128x128 tile, K=512 in 8 chunks of 64.
// cp.async double-buffered; fragments software-pipelined:
//   A frags loaded one s-step ahead, B frags one j2 ahead.
// 8 warps: warp tile 32(M) x 64(N).
// ---------------------------------------------------------------------------
#define BUFH  (128 * SROW)       // halves per buffer (per operand)
#define SSTEP (32 * SROW * 2)    // smem bytes between staging seg rows
#define GSTEP (32 * DIM)         // gmem elems between staging seg rows
#define TSTR  (16 * SROW * 2)    // smem bytes between 16-row tiles

__device__ __forceinline__ void hgemm_tile(
    const __half* __restrict__ A, const __half* __restrict__ B,
    int m0, int n0, float acc[2][8][4])
{
    __shared__ __align__(16) __half sA[2][BUFH];
    __shared__ __align__(16) __half sB[2][BUFH];

    const int tid = threadIdx.x;
    const int lane = tid & 31, wid = tid >> 5;
    const int wm = (wid & 3) * 32, wn = (wid >> 2) * 64;

    const uint32_t aBase = smem_u32(&sA[0][0]);
    const uint32_t bBase = smem_u32(&sB[0][0]);

    // cp.async: one base per operand, constant strides
    const __half* gA0 = A + (m0 + (tid >> 3)) * DIM + (tid & 7) * 8;
    const __half* gB0 = B + (n0 + (tid >> 3)) * DIM + (tid & 7) * 8;
    const uint32_t stA0 = aBase + (tid >> 3) * (SROW * 2) + (tid & 7) * 16;
    const uint32_t stB0 = bBase + (tid >> 3) * (SROW * 2) + (tid & 7) * 16;

    // ldmatrix lane addressing
    const int la = lane & 7;
    const uint32_t aFrag0 = aBase + (wm + la + ((lane & 8) ? 8 : 0)) * (SROW * 2)
                          + (((lane & 16) ? 8 : 0)) * 2;
    const uint32_t bFrag0 = bBase + (wn + la + ((lane & 16) ? 8 : 0)) * (SROW * 2)
                          + (((lane & 8) ? 8 : 0)) * 2;

    // prologue: chunk 0 -> buf 0
    #pragma unroll
    for (int i = 0; i < 4; ++i) {
        cp_async16(stA0 + i * SSTEP, gA0 + i * GSTEP);
        cp_async16(stB0 + i * SSTEP, gB0 + i * GSTEP);
    }
    cp_commit();

    #pragma unroll 1
    for (int ch = 0; ch < 8; ++ch) {
        cp_wait0();
        __syncthreads();

        if (ch < 7) {
            const uint32_t bo = ((ch + 1) & 1) * (BUFH * 2);
            const int ko = (ch + 1) * 64;
            #pragma unroll
            for (int i = 0; i < 4; ++i) {
                cp_async16(stA0 + bo + i * SSTEP, gA0 + ko + i * GSTEP);
                cp_async16(stB0 + bo + i * SSTEP, gB0 + ko + i * GSTEP);
            }
            cp_commit();
        }

        const uint32_t aF = aFrag0 + (ch & 1) * (BUFH * 2);
        const uint32_t bF = bFrag0 + (ch & 1) * (BUFH * 2);

        // preload s=0 fragments
        uint32_t aCur[2][4], aNxt[2][4], rbCur[4], rbNxt[4];
        ldsm_x4(aCur[0], aF);
        ldsm_x4(aCur[1], aF + TSTR);
        ldsm_x4(rbCur, bF);

        #pragma unroll
        for (int s = 0; s < 4; ++s) {
            const uint32_t kb = s * 32;
            if (s < 3) {                     // A for next s-step
                ldsm_x4(aNxt[0], aF + kb + 32);
                ldsm_x4(aNxt[1], aF + kb + 32 + TSTR);
            }
            #pragma unroll
            for (int j2 = 0; j2 < 4; ++j2) {
                if (j2 < 3)                  // B for next j2
                    ldsm_x4(rbNxt, bF + kb + (j2 + 1) * TSTR);
                else if (s < 3)              // first B of next s-step
                    ldsm_x4(rbNxt, bF + kb + 32);
                mma16816(acc[0][2 * j2 + 0], aCur[0], rbCur[0], rbCur[1]);
                mma16816(acc[0][2 * j2 + 1], aCur[0], rbCur[2], rbCur[3]);
                mma16816(acc[1][2 * j2 + 0], aCur[1], rbCur[0], rbCur[1]);
                mma16816(acc[1][2 * j2 + 1], aCur[1], rbCur[2], rbCur[3]);
                #pragma unroll
                for (int q = 0; q < 4; ++q) rbCur[q] = rbNxt[q];
            }
            #pragma unroll
            for (int q = 0; q < 4; ++q) {
                aCur[0][q] = aNxt[0][q];
                aCur[1][q] = aNxt[1][q];
            }
        }
    }
}

// ---------------------------------------------------------------------------
// Kernel: QKV GEMM. epilogue: +bias -> fp16 Q (pre-scaled), K, V^T
// ---------------------------------------------------------------------------
__global__ __launch_bounds__(256, 2)
void qkv_hgemm_kernel(const float* __restrict__ bias)
{
    float acc[2][8][4] = {};
    const int m0 = blockIdx.y * 128, n0 = blockIdx.x * 128;
    hgemm_tile(g_x, g_wq, m0, n0, acc);

    const int tid = threadIdx.x, lane = tid & 31, wid = tid >> 5;
    const int g = lane >> 2, t = lane & 3;
    const int wm = (wid & 3) * 32, wn = (wid >> 2) * 64;
    const float scale = 0.1767766952966369f;   // 32^-0.5

    #pragma unroll
    for (int i = 0; i < 2; ++i) {
        #pragma unroll
        for (int h = 0; h < 2; ++h) {
            const int m = m0 + wm + i * 16 + h * 8 + g;
            const int win = m / NTOK, tok = m % NTOK;
            #pragma unroll
            for (int j = 0; j < 8; ++j) {
                const int n = n0 + wn + j * 8 + 2 * t;
                const int sel = n >> 9, head = (n >> 5) & 15, d = n & 31;
                const int wh = (win << 4) + head;
                float vx = acc[i][j][h * 2 + 0] + bias[n + 0];
                float vy = acc[i][j][h * 2 + 1] + bias[n + 1];
                if (sel == 0) {
                    *(__half2*)&g_qh[(wh * NTOK + tok) * HDIM + d] =
                        __floats2half2_rn(vx * scale, vy * scale);
                } else if (sel == 1) {
                    *(__half2*)&g_kh[(wh * NTOK + tok) * HDIM + d] =
                        __floats2half2_rn(vx, vy);
                } else {
                    g_vT[(wh * HDIM + d    ) * NTOK + tok] = __float2half(vx);
                    g_vT[(wh * HDIM + d + 1) * NTOK + tok] = __float2half(vy);
                }
            }
        }
    }
}

// ---------------------------------------------------------------------------
// Kernel: tensor-core attention (proven R7). 1 block per (win,head), 96 thr.
// ---------------------------------------------------------------------------
#define QROW 40
#define VROW 152

__global__ __launch_bounds__(96)
void attn_mma_kernel()
{
    __shared__ __align__(16) __half sQ[NTOK * QROW];
    __shared__ __align__(16) __half sK[NTOK * QROW];
    __shared__ __align__(16) __half sVT[HDIM * VROW];

    const int wh = blockIdx.x;
    const int tid = threadIdx.x, lane = tid & 31, wid = tid >> 5;
    const int g = lane >> 2, t = lane & 3;

    const __half* qp = g_qh + wh * (NTOK * HDIM);
    const __half* kp = g_kh + wh * (NTOK * HDIM);
    const __half* vp = g_vT + wh * (HDIM * NTOK);

    for (int seg = tid; seg < 576; seg += 96) {
        int row = seg >> 2, sub = seg & 3;
        *(uint4*)&sQ[row * QROW + sub * 8] = *(const uint4*)(qp + row * HDIM + sub * 8);
        *(uint4*)&sK[row * QROW + sub * 8] = *(const uint4*)(kp + row * HDIM + sub * 8);
        int vrow = seg / 18, vsub = seg - vrow * 18;
        *(uint4*)&sVT[vrow * VROW + vsub * 8] = *(const uint4*)(vp + vrow * NTOK + vsub * 8);
    }
    __syncthreads();

    const int win = wh >> 4, head = wh & 15;

    #pragma unroll 1
    for (int ti = 0; ti < 3; ++ti) {
        const int tile = wid * 3 + ti;
        const int r = tile * 16 + g;

        uint32_t qa[2][4];
        #pragma unroll
        for (int s = 0; s < 2; ++s) {
            const int c = s * 16 + 2 * t;
            qa[s][0] = *(const uint32_t*)&sQ[ r      * QROW + c    ];
            qa[s][1] = *(const uint32_t*)&sQ[(r + 8) * QROW + c    ];
            qa[s][2] = *(const uint32_t*)&sQ[ r      * QROW + c + 8];
            qa[s][3] = *(const uint32_t*)&sQ[(r + 8) * QROW + c + 8];
        }

        uint32_t eh[18][2];
        float sum0 = 0.f, sum1 = 0.f;
        #pragma unroll
        for (int j = 0; j < 18; ++j) {
            float sc[4] = {};
            const int rn = 8 * j + g;
            #pragma unroll
            for (int s = 0; s < 2; ++s) {
                const int c = s * 16 + 2 * t;
                uint32_t b0 = *(const uint32_t*)&sK[rn * QROW + c    ];
                uint32_t b1 = *(const uint32_t*)&sK[rn * QROW + c + 8];
                mma16816(sc, qa[s], b0, b1);
            }
            float e0 = __expf(sc[0]), e1 = __expf(sc[1]);
            float e2 = __expf(sc[2]), e3 = __expf(sc[3]);
            sum0 += e0 + e1; sum1 += e2 + e3;
            __half2 p01 = __floats2half2_rn(e0, e1);
            __half2 p23 = __floats2half2_rn(e2, e3);
            eh[j][0] = *(uint32_t*)&p01;
            eh[j][1] = *(uint32_t*)&p23;
        }
        sum0 += __shfl_xor_sync(0xffffffffu, sum0, 1);
        sum0 += __shfl_xor_sync(0xffffffffu, sum0, 2);
        sum1 += __shfl_xor_sync(0xffffffffu, sum1, 1);
        sum1 += __shfl_xor_sync(0xffffffffu, sum1, 2);

        float acc[4][4] = {};
        #pragma unroll
        for (int kk = 0; kk < 9; ++kk) {
            uint32_t a[4] = {eh[2 * kk][0], eh[2 * kk][1],
                             eh[2 * kk + 1][0], eh[2 * kk + 1][1]};
            #pragma unroll
            for (int nd = 0; nd < 4; ++nd) {
                const int rn = 8 * nd + g;
                uint32_t b0 = *(const uint32_t*)&sVT[rn * VROW + kk * 16 + 2 * t    ];
                uint32_t b1 = *(const uint32_t*)&sVT[rn * VROW + kk * 16 + 2 * t + 8];
                mma16816(acc[nd], a, b0, b1);
            }
        }

        const float inv0 = 1.f / sum0, inv1 = 1.f / sum1;
        __half* o0 = g_ao + (win * NTOK + r) * DIM + head * HDIM;
        __half* o1 = o0 + 8 * DIM;
        #pragma unroll
        for (int nd = 0; nd < 4; ++nd) {
            const int d = 8 * nd + 2 * t;
            *(__half2*)&o0[d] = __floats2half2_rn(acc[nd][0] * inv0, acc[nd][1] * inv0);
            *(__half2*)&o1[d] = __floats2half2_rn(acc[nd][2] * inv1, acc[nd][3] * inv1);
        }
    }
}

// ---------------------------------------------------------------------------
// Kernel: proj GEMM. epilogue: +bias, window_reverse scatter -> out fp32
// ---------------------------------------------------------------------------
__global__ __launch_bounds__(256, 2)
void proj_hgemm_kernel(const float* __restrict__ bias, float* __restrict__ out)
{
    float acc[2][8][4] = {};
    const int m0 = blockIdx.y * 128, n0 = blockIdx.x * 128;
    hgemm_tile(g_ao, g_wp, m0, n0, acc);

    const int tid = threadIdx.x, lane = tid & 31, wid = tid >> 5;
    const int g = lane >> 2, t = lane & 3;
    const int wm = (wid & 3) * 32, wn = (wid >> 2) * 64;

    #pragma unroll
    for (int i = 0; i < 2; ++i) {
        #pragma unroll
        for (int h = 0; h < 2; ++h) {
            const int m = m0 + wm + i * 16 + h * 8 + g;
            const int win = m / NTOK, tok = m % NTOK;
            const int b = win >> 4, yw = (win >> 2) & 3, xw = win & 3;
            const int y = yw * 12 + tok / 12;
            const int x = xw * 12 + tok % 12;
            float* orow = out + ((b * 2304 + y * 48 + x) << 9);
            #pragma unroll
            for (int j = 0; j < 8; ++j) {
                const int n = n0 + wn + j * 8 + 2 * t;
                float2 v;
                v.x = acc[i][j][h * 2 + 0] + bias[n + 0];
                v.y = acc[i][j][h * 2 + 1] + bias[n + 1];
                *(float2*)&orow[n] = v;
            }
        }
    }
}

// ---------------------------------------------------------------------------
extern "C" void kernel_launch(void* const* d_in, const int* in_sizes, int n_in,
                              void* d_out, int out_size)
{
    const float* hidden = (const float*)d_in[0];
    const float* qkv_w  = (const float*)d_in[1];
    const float* qkv_b  = (const float*)d_in[2];
    const float* proj_w = (const float*)d_in[3];
    const float* proj_b = (const float*)d_in[4];
    float* out = (float*)d_out;

    convert_x_kernel<<<MTOT * 64 / 256, 256>>>(hidden);
    convert_w_kernel<<<dim3(NQKV / 32 + DIM / 32, DIM / 32), dim3(32, 8)>>>(qkv_w, proj_w);

    qkv_hgemm_kernel<<<dim3(NQKV / 128, MTOT / 128), 256>>>(qkv_b);

    attn_mma_kernel<<<NWIN * NHEAD, 96>>>();

    proj_hgemm_kernel<<<dim3(DIM / 128, MTOT / 128), 256>>>(proj_b, out);
}

// round 11
// speedup vs baseline: 1.0761x; 1.0761x over previous
#include <cuda_runtime.h>
#include <cuda_fp16.h>
#include <cstdint>

// ---------------------------------------------------------------------------
// Florence2 window attention — all matmuls on mma.sync (fp16 in, fp32 acc).
// R11: qkv uses 512-thread CTA (16 warps x 32x32 tiles) to double warps/SMSP;
// proj keeps the proven R9 256-thread loop; converts merged into one launch.
// ---------------------------------------------------------------------------

#define NWIN   128
#define NTOK   144
#define DIM    512
#define NHEAD  16
#define HDIM   32
#define MTOT   (NWIN * NTOK)     // 18432
#define NQKV   1536

#define SROW   72                // hgemm smem row stride in halves (144B)
#define BUFH  (128 * SROW)       // halves per buffer (per operand)
#define TSTR  (16 * SROW * 2)    // smem bytes between 16-row tiles

// ---------------- scratch (device globals; device-code refs only) ----------
__device__ __align__(16) __half g_x  [MTOT * DIM];
__device__ __align__(16) __half g_wq [NQKV * DIM];
__device__ __align__(16) __half g_wp [DIM * DIM];
__device__ __align__(16) __half g_qh [NWIN * NHEAD * NTOK * HDIM];
__device__ __align__(16) __half g_kh [NWIN * NHEAD * NTOK * HDIM];
__device__ __align__(16) __half g_vT [NWIN * NHEAD * HDIM * NTOK];
__device__ __align__(16) __half g_ao [MTOT * DIM];

// ---------------- PTX helpers ----------------------------------------------
__device__ __forceinline__ uint32_t smem_u32(const void* p) {
    uint32_t a;
    asm("{ .reg .u64 t; cvta.to.shared.u64 t, %1; cvt.u32.u64 %0, t; }" : "=r"(a) : "l"(p));
    return a;
}
__device__ __forceinline__ void cp_async16(uint32_t s, const void* g) {
    asm volatile("cp.async.cg.shared.global [%0], [%1], 16;" :: "r"(s), "l"(g));
}
__device__ __forceinline__ void cp_commit() { asm volatile("cp.async.commit_group;"); }
__device__ __forceinline__ void cp_wait0()  { asm volatile("cp.async.wait_group 0;"); }

__device__ __forceinline__ void ldsm_x4(uint32_t* r, uint32_t addr) {
    asm volatile("ldmatrix.sync.aligned.m8n8.x4.shared.b16 {%0,%1,%2,%3}, [%4];"
        : "=r"(r[0]), "=r"(r[1]), "=r"(r[2]), "=r"(r[3]) : "r"(addr));
}
__device__ __forceinline__ void mma16816(float* d, const uint32_t* a,
                                         uint32_t b0, uint32_t b1) {
    asm volatile("mma.sync.aligned.m16n8k16.row.col.f32.f16.f16.f32 "
        "{%0,%1,%2,%3}, {%4,%5,%6,%7}, {%8,%9}, {%0,%1,%2,%3};"
        : "+f"(d[0]), "+f"(d[1]), "+f"(d[2]), "+f"(d[3])
        : "r"(a[0]), "r"(a[1]), "r"(a[2]), "r"(a[3]), "r"(b0), "r"(b1));
}

__device__ __forceinline__ int hidden_row_off(int m) {
    int win = m / NTOK, t = m % NTOK;
    int b = win >> 4, yw = (win >> 2) & 3, xw = win & 3;
    int y = yw * 12 + t / 12;
    int x = xw * 12 + t % 12;
    return ((b * 48 + y) * 48 + x) * DIM;
}

// ---------------------------------------------------------------------------
// merged conversion kernel: blocks [0, NXB) convert X; rest transpose weights
// ---------------------------------------------------------------------------
#define NXB (MTOT * 64 / 256)            // 4608
#define NWB ((NQKV / 32 + DIM / 32) * (DIM / 32))   // 1024

__global__ void convert_all_kernel(const float* __restrict__ hidden,
                                   const float* __restrict__ Wq,
                                   const float* __restrict__ Wp) {
    const int tid = threadIdx.x;
    if (blockIdx.x < NXB) {
        int idx = blockIdx.x * 256 + tid;
        int m = idx >> 6, seg = idx & 63;
        const float* src = hidden + hidden_row_off(m) + seg * 8;
        float4 f0 = *(const float4*)src;
        float4 f1 = *(const float4*)(src + 4);
        __align__(16) __half h[8];
        h[0] = __float2half(f0.x); h[1] = __float2half(f0.y);
        h[2] = __float2half(f0.z); h[3] = __float2half(f0.w);
        h[4] = __float2half(f1.x); h[5] = __float2half(f1.y);
        h[6] = __float2half(f1.z); h[7] = __float2half(f1.w);
        *(uint4*)&g_x[m * DIM + seg * 8] = *(uint4*)h;
        return;
    }
    __shared__ float t[32][33];
    const int r = blockIdx.x - NXB;
    const int bx = r & 63, by = r >> 6;
    const bool isP = bx >= (NQKV / 32);
    const float* __restrict__ W = isP ? Wp : Wq;
    const int N = isP ? DIM : NQKV;
    __half* __restrict__ outT = isP ? g_wp : g_wq;
    const int n0 = (isP ? bx - NQKV / 32 : bx) * 32;
    const int k0 = by * 32;
    const int tx = tid & 31, ty = tid >> 5;   // 32 x 8
    #pragma unroll
    for (int j = 0; j < 4; ++j)
        t[ty + 8 * j][tx] = W[(k0 + ty + 8 * j) * N + n0 + tx];
    __syncthreads();
    #pragma unroll
    for (int j = 0; j < 4; ++j)
        outT[(n0 + ty + 8 * j) * DIM + k0 + tx] = __float2half(t[tx][ty + 8 * j]);
}

// ---------------------------------------------------------------------------
// Kernel: QKV GEMM — 512 threads, 16 warps, warp tile 32(M) x 32(N).
// R9-style pipeline: wait0 -> sync -> prefetch(ch+1) -> compute(ch).
// ---------------------------------------------------------------------------
__global__ __launch_bounds__(512, 2)
void qkv_hgemm_kernel(const float* __restrict__ bias)
{
    __shared__ __align__(16) __half sA[2][BUFH];
    __shared__ __align__(16) __half sB[2][BUFH];

    const int tid = threadIdx.x;
    const int lane = tid & 31, wid = tid >> 5;
    const int wm = (wid & 3) * 32, wn = (wid >> 2) * 32;
    const int m0 = blockIdx.y * 128, n0 = blockIdx.x * 128;

    const uint32_t aBase = smem_u32(&sA[0][0]);
    const uint32_t bBase = smem_u32(&sB[0][0]);

    // cp.async: 2 x 16B segments per operand per thread (rows tid>>3, 64+tid>>3)
    const __half* gA0 = g_x  + (m0 + (tid >> 3)) * DIM + (tid & 7) * 8;
    const __half* gB0 = g_wq + (n0 + (tid >> 3)) * DIM + (tid & 7) * 8;
    const uint32_t stA0 = aBase + (tid >> 3) * (SROW * 2) + (tid & 7) * 16;
    const uint32_t stB0 = bBase + (tid >> 3) * (SROW * 2) + (tid & 7) * 16;
    const int GS2 = 64 * DIM;            // gmem elems between the 2 segs
    const int SS2 = 64 * SROW * 2;       // smem bytes between the 2 segs

    // ldmatrix lane addressing
    const int la = lane & 7;
    const uint32_t aFrag0 = aBase + (wm + la + ((lane & 8) ? 8 : 0)) * (SROW * 2)
                          + (((lane & 16) ? 8 : 0)) * 2;
    const uint32_t bFrag0 = bBase + (wn + la + ((lane & 16) ? 8 : 0)) * (SROW * 2)
                          + (((lane & 8) ? 8 : 0)) * 2;

    float acc[2][4][4] = {};

    // prologue: chunk 0 -> buf 0
    cp_async16(stA0, gA0);             cp_async16(stB0, gB0);
    cp_async16(stA0 + SS2, gA0 + GS2); cp_async16(stB0 + SS2, gB0 + GS2);
    cp_commit();

    #pragma unroll 1
    for (int ch = 0; ch < 8; ++ch) {
        cp_wait0();
        __syncthreads();

        if (ch < 7) {
            const uint32_t bo = ((ch + 1) & 1) * (BUFH * 2);
            const int ko = (ch + 1) * 64;
            cp_async16(stA0 + bo, gA0 + ko);
            cp_async16(stB0 + bo, gB0 + ko);
            cp_async16(stA0 + bo + SS2, gA0 + ko + GS2);
            cp_async16(stB0 + bo + SS2, gB0 + ko + GS2);
            cp_commit();
        }

        const uint32_t aF = aFrag0 + (ch & 1) * (BUFH * 2);
        const uint32_t bF = bFrag0 + (ch & 1) * (BUFH * 2);
        #pragma unroll
        for (int s = 0; s < 4; ++s) {
            const uint32_t kb = s * 32;
            uint32_t a[2][4], b[2][4];
            ldsm_x4(a[0], aF + kb);
            ldsm_x4(a[1], aF + kb + TSTR);
            ldsm_x4(b[0], bF + kb);
            ldsm_x4(b[1], bF + kb + TSTR);
            #pragma unroll
            for (int i = 0; i < 2; ++i) {
                mma16816(acc[i][0], a[i], b[0][0], b[0][1]);
                mma16816(acc[i][1], a[i], b[0][2], b[0][3]);
                mma16816(acc[i][2], a[i], b[1][0], b[1][1]);
                mma16816(acc[i][3], a[i], b[1][2], b[1][3]);
            }
        }
    }

    // epilogue: +bias -> fp16 Q (pre-scaled), K, V^T
    const int g = lane >> 2, t = lane & 3;
    const float scale = 0.1767766952966369f;   // 32^-0.5
    #pragma unroll
    for (int i = 0; i < 2; ++i) {
        #pragma unroll
        for (int h = 0; h < 2; ++h) {
            const int m = m0 + wm + i * 16 + h * 8 + g;
            const int win = m / NTOK, tok = m % NTOK;
            #pragma unroll
            for (int j = 0; j < 4; ++j) {
                const int n = n0 + wn + j * 8 + 2 * t;
                const int sel = n >> 9, head = (n >> 5) & 15, d = n & 31;
                const int wh = (win << 4) + head;
                float vx = acc[i][j][h * 2 + 0] + bias[n + 0];
                float vy = acc[i][j][h * 2 + 1] + bias[n + 1];
                if (sel == 0) {
                    *(__half2*)&g_qh[(wh * NTOK + tok) * HDIM + d] =
                        __floats2half2_rn(vx * scale, vy * scale);
                } else if (sel == 1) {
                    *(__half2*)&g_kh[(wh * NTOK + tok) * HDIM + d] =
                        __floats2half2_rn(vx, vy);
                } else {
                    g_vT[(wh * HDIM + d    ) * NTOK + tok] = __float2half(vx);
                    g_vT[(wh * HDIM + d + 1) * NTOK + tok] = __float2half(vy);
                }
            }
        }
    }
}

// ---------------------------------------------------------------------------
// Kernel: tensor-core attention (proven R7). 1 block per (win,head), 96 thr.
// ---------------------------------------------------------------------------
#define QROW 40
#define VROW 152

__global__ __launch_bounds__(96)
void attn_mma_kernel()
{
    __shared__ __align__(16) __half sQ[NTOK * QROW];
    __shared__ __align__(16) __half sK[NTOK * QROW];
    __shared__ __align__(16) __half sVT[HDIM * VROW];

    const int wh = blockIdx.x;
    const int tid = threadIdx.x, lane = tid & 31, wid = tid >> 5;
    const int g = lane >> 2, t = lane & 3;

    const __half* qp = g_qh + wh * (NTOK * HDIM);
    const __half* kp = g_kh + wh * (NTOK * HDIM);
    const __half* vp = g_vT + wh * (HDIM * NTOK);

    for (int seg = tid; seg < 576; seg += 96) {
        int row = seg >> 2, sub = seg & 3;
        *(uint4*)&sQ[row * QROW + sub * 8] = *(const uint4*)(qp + row * HDIM + sub * 8);
        *(uint4*)&sK[row * QROW + sub * 8] = *(const uint4*)(kp + row * HDIM + sub * 8);
        int vrow = seg / 18, vsub = seg - vrow * 18;
        *(uint4*)&sVT[vrow * VROW + vsub * 8] = *(const uint4*)(vp + vrow * NTOK + vsub * 8);
    }
    __syncthreads();

    const int win = wh >> 4, head = wh & 15;

    #pragma unroll 1
    for (int ti = 0; ti < 3; ++ti) {
        const int tile = wid * 3 + ti;
        const int r = tile * 16 + g;

        uint32_t qa[2][4];
        #pragma unroll
        for (int s = 0; s < 2; ++s) {
            const int c = s * 16 + 2 * t;
            qa[s][0] = *(const uint32_t*)&sQ[ r      * QROW + c    ];
            qa[s][1] = *(const uint32_t*)&sQ[(r + 8) * QROW + c    ];
            qa[s][2] = *(const uint32_t*)&sQ[ r      * QROW + c + 8];
            qa[s][3] = *(const uint32_t*)&sQ[(r + 8) * QROW + c + 8];
        }

        uint32_t eh[18][2];
        float sum0 = 0.f, sum1 = 0.f;
        #pragma unroll
        for (int j = 0; j < 18; ++j) {
            float sc[4] = {};
            const int rn = 8 * j + g;
            #pragma unroll
            for (int s = 0; s < 2; ++s) {
                const int c = s * 16 + 2 * t;
                uint32_t b0 = *(const uint32_t*)&sK[rn * QROW + c    ];
                uint32_t b1 = *(const uint32_t*)&sK[rn * QROW + c + 8];
                mma16816(sc, qa[s], b0, b1);
            }
            float e0 = __expf(sc[0]), e1 = __expf(sc[1]);
            float e2 = __expf(sc[2]), e3 = __expf(sc[3]);
            sum0 += e0 + e1; sum1 += e2 + e3;
            __half2 p01 = __floats2half2_rn(e0, e1);
            __half2 p23 = __floats2half2_rn(e2, e3);
            eh[j][0] = *(uint32_t*)&p01;
            eh[j][1] = *(uint32_t*)&p23;
        }
        sum0 += __shfl_xor_sync(0xffffffffu, sum0, 1);
        sum0 += __shfl_xor_sync(0xffffffffu, sum0, 2);
        sum1 += __shfl_xor_sync(0xffffffffu, sum1, 1);
        sum1 += __shfl_xor_sync(0xffffffffu, sum1, 2);

        float acc[4][4] = {};
        #pragma unroll
        for (int kk = 0; kk < 9; ++kk) {
            uint32_t a[4] = {eh[2 * kk][0], eh[2 * kk][1],
                             eh[2 * kk + 1][0], eh[2 * kk + 1][1]};
            #pragma unroll
            for (int nd = 0; nd < 4; ++nd) {
                const int rn = 8 * nd + g;
                uint32_t b0 = *(const uint32_t*)&sVT[rn * VROW + kk * 16 + 2 * t    ];
                uint32_t b1 = *(const uint32_t*)&sVT[rn * VROW + kk * 16 + 2 * t + 8];
                mma16816(acc[nd], a, b0, b1);
            }
        }

        const float inv0 = 1.f / sum0, inv1 = 1.f / sum1;
        __half* o0 = g_ao + (win * NTOK + r) * DIM + head * HDIM;
        __half* o1 = o0 + 8 * DIM;
        #pragma unroll
        for (int nd = 0; nd < 4; ++nd) {
            const int d = 8 * nd + 2 * t;
            *(__half2*)&o0[d] = __floats2half2_rn(acc[nd][0] * inv0, acc[nd][1] * inv0);
            *(__half2*)&o1[d] = __floats2half2_rn(acc[nd][2] * inv1, acc[nd][3] * inv1);
        }
    }
}

// ---------------------------------------------------------------------------
// Kernel: proj GEMM — proven R9 256-thread loop (8 warps x 32x64 tiles).
// ---------------------------------------------------------------------------
__global__ __launch_bounds__(256, 2)
void proj_hgemm_kernel(const float* __restrict__ bias, float* __restrict__ out)
{
    __shared__ __align__(16) __half sA[2][BUFH];
    __shared__ __align__(16) __half sB[2][BUFH];

    const int tid = threadIdx.x;
    const int lane = tid & 31, wid = tid >> 5;
    const int wm = (wid & 3) * 32, wn = (wid >> 2) * 64;
    const int m0 = blockIdx.y * 128, n0 = blockIdx.x * 128;

    const uint32_t aBase = smem_u32(&sA[0][0]);
    const uint32_t bBase = smem_u32(&sB[0][0]);

    const __half* gA0 = g_ao + (m0 + (tid >> 3)) * DIM + (tid & 7) * 8;
    const __half* gB0 = g_wp + (n0 + (tid >> 3)) * DIM + (tid & 7) * 8;
    const uint32_t stA0 = aBase + (tid >> 3) * (SROW * 2) + (tid & 7) * 16;
    const uint32_t stB0 = bBase + (tid >> 3) * (SROW * 2) + (tid & 7) * 16;
    const int GS = 32 * DIM;
    const int SS = 32 * SROW * 2;

    const int la = lane & 7;
    const uint32_t aFrag0 = aBase + (wm + la + ((lane & 8) ? 8 : 0)) * (SROW * 2)
                          + (((lane & 16) ? 8 : 0)) * 2;
    const uint32_t bFrag0 = bBase + (wn + la + ((lane & 16) ? 8 : 0)) * (SROW * 2)
                          + (((lane & 8) ? 8 : 0)) * 2;

    float acc[2][8][4] = {};

    #pragma unroll
    for (int i = 0; i < 4; ++i) {
        cp_async16(stA0 + i * SS, gA0 + i * GS);
        cp_async16(stB0 + i * SS, gB0 + i * GS);
    }
    cp_commit();

    #pragma unroll 1
    for (int ch = 0; ch < 8; ++ch) {
        cp_wait0();
        __syncthreads();

        if (ch < 7) {
            const uint32_t bo = ((ch + 1) & 1) * (BUFH * 2);
            const int ko = (ch + 1) * 64;
            #pragma unroll
            for (int i = 0; i < 4; ++i) {
                cp_async16(stA0 + bo + i * SS, gA0 + ko + i * GS);
                cp_async16(stB0 + bo + i * SS, gB0 + ko + i * GS);
            }
            cp_commit();
        }

        const uint32_t aF = aFrag0 + (ch & 1) * (BUFH * 2);
        const uint32_t bF = bFrag0 + (ch & 1) * (BUFH * 2);
        #pragma unroll
        for (int s = 0; s < 4; ++s) {
            const uint32_t kb = s * 32;
            uint32_t a[2][4];
            ldsm_x4(a[0], aF + kb);
            ldsm_x4(a[1], aF + kb + TSTR);
            #pragma unroll
            for (int j2 = 0; j2 < 4; ++j2) {
                uint32_t rb[4];
                ldsm_x4(rb, bF + kb + j2 * TSTR);
                mma16816(acc[0][2 * j2 + 0], a[0], rb[0], rb[1]);
                mma16816(acc[0][2 * j2 + 1], a[0], rb[2], rb[3]);
                mma16816(acc[1][2 * j2 + 0], a[1], rb[0], rb[1]);
                mma16816(acc[1][2 * j2 + 1], a[1], rb[2], rb[3]);
            }
        }
    }

    const int g = lane >> 2, t = lane & 3;
    #pragma unroll
    for (int i = 0; i < 2; ++i) {
        #pragma unroll
        for (int h = 0; h < 2; ++h) {
            const int m = m0 + wm + i * 16 + h * 8 + g;
            const int win = m / NTOK, tok = m % NTOK;
            const int b = win >> 4, yw = (win >> 2) & 3, xw = win & 3;
            const int y = yw * 12 + tok / 12;
            const int x = xw * 12 + tok % 12;
            float* orow = out + ((b * 2304 + y * 48 + x) << 9);
            #pragma unroll
            for (int j = 0; j < 8; ++j) {
                const int n = n0 + wn + j * 8 + 2 * t;
                float2 v;
                v.x = acc[i][j][h * 2 + 0] + bias[n + 0];
                v.y = acc[i][j][h * 2 + 1] + bias[n + 1];
                *(float2*)&orow[n] = v;
            }
        }
    }
}

// ---------------------------------------------------------------------------
extern "C" void kernel_launch(void* const* d_in, const int* in_sizes, int n_in,
                              void* d_out, int out_size)
{
    const float* hidden = (const float*)d_in[0];
    const float* qkv_w  = (const float*)d_in[1];
    const float* qkv_b  = (const float*)d_in[2];
    const float* proj_w = (const float*)d_in[3];
    const float* proj_b = (const float*)d_in[4];
    float* out = (float*)d_out;

    convert_all_kernel<<<NXB + NWB, 256>>>(hidden, qkv_w, proj_w);

    qkv_hgemm_kernel<<<dim3(NQKV / 128, MTOT / 128), 512>>>(qkv_b);

    attn_mma_kernel<<<NWIN * NHEAD, 96>>>();

    proj_hgemm_kernel<<<dim3(DIM / 128, MTOT / 128), 256>>>(proj_b, out);
}

// round 12
// speedup vs baseline: 1.0908x; 1.0136x over previous
#include <cuda_runtime.h>
#include <cuda_fp16.h>
#include <cstdint>

// ---------------------------------------------------------------------------
// Florence2 window attention — all matmuls on mma.sync (fp16 in, fp32 acc).
// R12: proj moved to 512-thread/16-warp config (the lever that won on qkv);
// attn drops its sQ smem staging (direct LDG Q fragments) to raise occupancy.
// ---------------------------------------------------------------------------

#define NWIN   128
#define NTOK   144
#define DIM    512
#define NHEAD  16
#define HDIM   32
#define MTOT   (NWIN * NTOK)     // 18432
#define NQKV   1536

#define SROW   72                // hgemm smem row stride in halves (144B)
#define BUFH  (128 * SROW)       // halves per buffer (per operand)
#define TSTR  (16 * SROW * 2)    // smem bytes between 16-row tiles

// ---------------- scratch (device globals; device-code refs only) ----------
__device__ __align__(16) __half g_x  [MTOT * DIM];
__device__ __align__(16) __half g_wq [NQKV * DIM];
__device__ __align__(16) __half g_wp [DIM * DIM];
__device__ __align__(16) __half g_qh [NWIN * NHEAD * NTOK * HDIM];
__device__ __align__(16) __half g_kh [NWIN * NHEAD * NTOK * HDIM];
__device__ __align__(16) __half g_vT [NWIN * NHEAD * HDIM * NTOK];
__device__ __align__(16) __half g_ao [MTOT * DIM];

// ---------------- PTX helpers ----------------------------------------------
__device__ __forceinline__ uint32_t smem_u32(const void* p) {
    uint32_t a;
    asm("{ .reg .u64 t; cvta.to.shared.u64 t, %1; cvt.u32.u64 %0, t; }" : "=r"(a) : "l"(p));
    return a;
}
__device__ __forceinline__ void cp_async16(uint32_t s, const void* g) {
    asm volatile("cp.async.cg.shared.global [%0], [%1], 16;" :: "r"(s), "l"(g));
}
__device__ __forceinline__ void cp_commit() { asm volatile("cp.async.commit_group;"); }
__device__ __forceinline__ void cp_wait0()  { asm volatile("cp.async.wait_group 0;"); }

__device__ __forceinline__ void ldsm_x4(uint32_t* r, uint32_t addr) {
    asm volatile("ldmatrix.sync.aligned.m8n8.x4.shared.b16 {%0,%1,%2,%3}, [%4];"
        : "=r"(r[0]), "=r"(r[1]), "=r"(r[2]), "=r"(r[3]) : "r"(addr));
}
__device__ __forceinline__ void mma16816(float* d, const uint32_t* a,
                                         uint32_t b0, uint32_t b1) {
    asm volatile("mma.sync.aligned.m16n8k16.row.col.f32.f16.f16.f32 "
        "{%0,%1,%2,%3}, {%4,%5,%6,%7}, {%8,%9}, {%0,%1,%2,%3};"
        : "+f"(d[0]), "+f"(d[1]), "+f"(d[2]), "+f"(d[3])
        : "r"(a[0]), "r"(a[1]), "r"(a[2]), "r"(a[3]), "r"(b0), "r"(b1));
}

__device__ __forceinline__ int hidden_row_off(int m) {
    int win = m / NTOK, t = m % NTOK;
    int b = win >> 4, yw = (win >> 2) & 3, xw = win & 3;
    int y = yw * 12 + t / 12;
    int x = xw * 12 + t % 12;
    return ((b * 48 + y) * 48 + x) * DIM;
}

// ---------------------------------------------------------------------------
// merged conversion kernel: blocks [0, NXB) convert X; rest transpose weights
// ---------------------------------------------------------------------------
#define NXB (MTOT * 64 / 256)            // 4608
#define NWB ((NQKV / 32 + DIM / 32) * (DIM / 32))   // 1024

__global__ void convert_all_kernel(const float* __restrict__ hidden,
                                   const float* __restrict__ Wq,
                                   const float* __restrict__ Wp) {
    const int tid = threadIdx.x;
    if (blockIdx.x < NXB) {
        int idx = blockIdx.x * 256 + tid;
        int m = idx >> 6, seg = idx & 63;
        const float* src = hidden + hidden_row_off(m) + seg * 8;
        float4 f0 = *(const float4*)src;
        float4 f1 = *(const float4*)(src + 4);
        __align__(16) __half h[8];
        h[0] = __float2half(f0.x); h[1] = __float2half(f0.y);
        h[2] = __float2half(f0.z); h[3] = __float2half(f0.w);
        h[4] = __float2half(f1.x); h[5] = __float2half(f1.y);
        h[6] = __float2half(f1.z); h[7] = __float2half(f1.w);
        *(uint4*)&g_x[m * DIM + seg * 8] = *(uint4*)h;
        return;
    }
    __shared__ float t[32][33];
    const int r = blockIdx.x - NXB;
    const int bx = r & 63, by = r >> 6;
    const bool isP = bx >= (NQKV / 32);
    const float* __restrict__ W = isP ? Wp : Wq;
    const int N = isP ? DIM : NQKV;
    __half* __restrict__ outT = isP ? g_wp : g_wq;
    const int n0 = (isP ? bx - NQKV / 32 : bx) * 32;
    const int k0 = by * 32;
    const int tx = tid & 31, ty = tid >> 5;   // 32 x 8
    #pragma unroll
    for (int j = 0; j < 4; ++j)
        t[ty + 8 * j][tx] = W[(k0 + ty + 8 * j) * N + n0 + tx];
    __syncthreads();
    #pragma unroll
    for (int j = 0; j < 4; ++j)
        outT[(n0 + ty + 8 * j) * DIM + k0 + tx] = __float2half(t[tx][ty + 8 * j]);
}

// ---------------------------------------------------------------------------
// 512-thread HGEMM mainloop (16 warps, warp tile 32x32), R11-proven.
// Computes acc for tile (m0,n0) of A[m][k] x B[n][k]^T.
// ---------------------------------------------------------------------------
__device__ __forceinline__ void hgemm512_tile(
    const __half* __restrict__ A, const __half* __restrict__ B,
    int m0, int n0, float acc[2][4][4],
    __half (*sA)[BUFH], __half (*sB)[BUFH])
{
    const int tid = threadIdx.x;
    const int lane = tid & 31, wid = tid >> 5;
    const int wm = (wid & 3) * 32, wn = (wid >> 2) * 32;

    const uint32_t aBase = smem_u32(&sA[0][0]);
    const uint32_t bBase = smem_u32(&sB[0][0]);

    const __half* gA0 = A + (m0 + (tid >> 3)) * DIM + (tid & 7) * 8;
    const __half* gB0 = B + (n0 + (tid >> 3)) * DIM + (tid & 7) * 8;
    const uint32_t stA0 = aBase + (tid >> 3) * (SROW * 2) + (tid & 7) * 16;
    const uint32_t stB0 = bBase + (tid >> 3) * (SROW * 2) + (tid & 7) * 16;
    const int GS2 = 64 * DIM;
    const int SS2 = 64 * SROW * 2;

    const int la = lane & 7;
    const uint32_t aFrag0 = aBase + (wm + la + ((lane & 8) ? 8 : 0)) * (SROW * 2)
                          + (((lane & 16) ? 8 : 0)) * 2;
    const uint32_t bFrag0 = bBase + (wn + la + ((lane & 16) ? 8 : 0)) * (SROW * 2)
                          + (((lane & 8) ? 8 : 0)) * 2;

    cp_async16(stA0, gA0);             cp_async16(stB0, gB0);
    cp_async16(stA0 + SS2, gA0 + GS2); cp_async16(stB0 + SS2, gB0 + GS2);
    cp_commit();

    #pragma unroll 1
    for (int ch = 0; ch < 8; ++ch) {
        cp_wait0();
        __syncthreads();

        if (ch < 7) {
            const uint32_t bo = ((ch + 1) & 1) * (BUFH * 2);
            const int ko = (ch + 1) * 64;
            cp_async16(stA0 + bo, gA0 + ko);
            cp_async16(stB0 + bo, gB0 + ko);
            cp_async16(stA0 + bo + SS2, gA0 + ko + GS2);
            cp_async16(stB0 + bo + SS2, gB0 + ko + GS2);
            cp_commit();
        }

        const uint32_t aF = aFrag0 + (ch & 1) * (BUFH * 2);
        const uint32_t bF = bFrag0 + (ch & 1) * (BUFH * 2);
        #pragma unroll
        for (int s = 0; s < 4; ++s) {
            const uint32_t kb = s * 32;
            uint32_t a[2][4], b[2][4];
            ldsm_x4(a[0], aF + kb);
            ldsm_x4(a[1], aF + kb + TSTR);
            ldsm_x4(b[0], bF + kb);
            ldsm_x4(b[1], bF + kb + TSTR);
            #pragma unroll
            for (int i = 0; i < 2; ++i) {
                mma16816(acc[i][0], a[i], b[0][0], b[0][1]);
                mma16816(acc[i][1], a[i], b[0][2], b[0][3]);
                mma16816(acc[i][2], a[i], b[1][0], b[1][1]);
                mma16816(acc[i][3], a[i], b[1][2], b[1][3]);
            }
        }
    }
}

// ---------------------------------------------------------------------------
// Kernel: QKV GEMM — 512 threads (R11-proven).
// ---------------------------------------------------------------------------
__global__ __launch_bounds__(512, 2)
void qkv_hgemm_kernel(const float* __restrict__ bias)
{
    __shared__ __align__(16) __half sA[2][BUFH];
    __shared__ __align__(16) __half sB[2][BUFH];

    float acc[2][4][4] = {};
    const int m0 = blockIdx.y * 128, n0 = blockIdx.x * 128;
    hgemm512_tile(g_x, g_wq, m0, n0, acc, sA, sB);

    const int tid = threadIdx.x, lane = tid & 31, wid = tid >> 5;
    const int g = lane >> 2, t = lane & 3;
    const int wm = (wid & 3) * 32, wn = (wid >> 2) * 32;
    const float scale = 0.1767766952966369f;   // 32^-0.5

    #pragma unroll
    for (int i = 0; i < 2; ++i) {
        #pragma unroll
        for (int h = 0; h < 2; ++h) {
            const int m = m0 + wm + i * 16 + h * 8 + g;
            const int win = m / NTOK, tok = m % NTOK;
            #pragma unroll
            for (int j = 0; j < 4; ++j) {
                const int n = n0 + wn + j * 8 + 2 * t;
                const int sel = n >> 9, head = (n >> 5) & 15, d = n & 31;
                const int wh = (win << 4) + head;
                float vx = acc[i][j][h * 2 + 0] + bias[n + 0];
                float vy = acc[i][j][h * 2 + 1] + bias[n + 1];
                if (sel == 0) {
                    *(__half2*)&g_qh[(wh * NTOK + tok) * HDIM + d] =
                        __floats2half2_rn(vx * scale, vy * scale);
                } else if (sel == 1) {
                    *(__half2*)&g_kh[(wh * NTOK + tok) * HDIM + d] =
                        __floats2half2_rn(vx, vy);
                } else {
                    g_vT[(wh * HDIM + d    ) * NTOK + tok] = __float2half(vx);
                    g_vT[(wh * HDIM + d + 1) * NTOK + tok] = __float2half(vy);
                }
            }
        }
    }
}

// ---------------------------------------------------------------------------
// Kernel: tensor-core attention. R12: Q fragments loaded directly from gmem
// (no sQ smem) -> smem 33KB -> 22KB -> ~10 CTAs/SM.
// ---------------------------------------------------------------------------
#define QROW 40     // sK row stride (halves)
#define VROW 152    // sVT row stride (halves)

__global__ __launch_bounds__(96)
void attn_mma_kernel()
{
    __shared__ __align__(16) __half sK[NTOK * QROW];
    __shared__ __align__(16) __half sVT[HDIM * VROW];

    const int wh = blockIdx.x;
    const int tid = threadIdx.x, lane = tid & 31, wid = tid >> 5;
    const int g = lane >> 2, t = lane & 3;

    const __half* qp = g_qh + wh * (NTOK * HDIM);
    const __half* kp = g_kh + wh * (NTOK * HDIM);
    const __half* vp = g_vT + wh * (HDIM * NTOK);

    for (int seg = tid; seg < 576; seg += 96) {
        int row = seg >> 2, sub = seg & 3;
        *(uint4*)&sK[row * QROW + sub * 8] = *(const uint4*)(kp + row * HDIM + sub * 8);
        int vrow = seg / 18, vsub = seg - vrow * 18;
        *(uint4*)&sVT[vrow * VROW + vsub * 8] = *(const uint4*)(vp + vrow * NTOK + vsub * 8);
    }
    __syncthreads();

    const int win = wh >> 4, head = wh & 15;

    #pragma unroll 1
    for (int ti = 0; ti < 3; ++ti) {
        const int tile = wid * 3 + ti;
        const int r = tile * 16 + g;

        // Q A-fragments straight from gmem (32-bit aligned, L2-hot)
        uint32_t qa[2][4];
        #pragma unroll
        for (int s = 0; s < 2; ++s) {
            const int c = s * 16 + 2 * t;
            qa[s][0] = *(const uint32_t*)&qp[ r      * HDIM + c    ];
            qa[s][1] = *(const uint32_t*)&qp[(r + 8) * HDIM + c    ];
            qa[s][2] = *(const uint32_t*)&qp[ r      * HDIM + c + 8];
            qa[s][3] = *(const uint32_t*)&qp[(r + 8) * HDIM + c + 8];
        }

        uint32_t eh[18][2];
        float sum0 = 0.f, sum1 = 0.f;
        #pragma unroll
        for (int j = 0; j < 18; ++j) {
            float sc[4] = {};
            const int rn = 8 * j + g;
            #pragma unroll
            for (int s = 0; s < 2; ++s) {
                const int c = s * 16 + 2 * t;
                uint32_t b0 = *(const uint32_t*)&sK[rn * QROW + c    ];
                uint32_t b1 = *(const uint32_t*)&sK[rn * QROW + c + 8];
                mma16816(sc, qa[s], b0, b1);
            }
            float e0 = __expf(sc[0]), e1 = __expf(sc[1]);
            float e2 = __expf(sc[2]), e3 = __expf(sc[3]);
            sum0 += e0 + e1; sum1 += e2 + e3;
            __half2 p01 = __floats2half2_rn(e0, e1);
            __half2 p23 = __floats2half2_rn(e2, e3);
            eh[j][0] = *(uint32_t*)&p01;
            eh[j][1] = *(uint32_t*)&p23;
        }
        sum0 += __shfl_xor_sync(0xffffffffu, sum0, 1);
        sum0 += __shfl_xor_sync(0xffffffffu, sum0, 2);
        sum1 += __shfl_xor_sync(0xffffffffu, sum1, 1);
        sum1 += __shfl_xor_sync(0xffffffffu, sum1, 2);

        float acc[4][4] = {};
        #pragma unroll
        for (int kk = 0; kk < 9; ++kk) {
            uint32_t a[4] = {eh[2 * kk][0], eh[2 * kk][1],
                             eh[2 * kk + 1][0], eh[2 * kk + 1][1]};
            #pragma unroll
            for (int nd = 0; nd < 4; ++nd) {
                const int rn = 8 * nd + g;
                uint32_t b0 = *(const uint32_t*)&sVT[rn * VROW + kk * 16 + 2 * t    ];
                uint32_t b1 = *(const uint32_t*)&sVT[rn * VROW + kk * 16 + 2 * t + 8];
                mma16816(acc[nd], a, b0, b1);
            }
        }

        const float inv0 = 1.f / sum0, inv1 = 1.f / sum1;
        __half* o0 = g_ao + (win * NTOK + r) * DIM + head * HDIM;
        __half* o1 = o0 + 8 * DIM;
        #pragma unroll
        for (int nd = 0; nd < 4; ++nd) {
            const int d = 8 * nd + 2 * t;
            *(__half2*)&o0[d] = __floats2half2_rn(acc[nd][0] * inv0, acc[nd][1] * inv0);
            *(__half2*)&o1[d] = __floats2half2_rn(acc[nd][2] * inv1, acc[nd][3] * inv1);
        }
    }
}

// ---------------------------------------------------------------------------
// Kernel: proj GEMM — 512 threads (same lever as qkv).
// ---------------------------------------------------------------------------
__global__ __launch_bounds__(512, 2)
void proj_hgemm_kernel(const float* __restrict__ bias, float* __restrict__ out)
{
    __shared__ __align__(16) __half sA[2][BUFH];
    __shared__ __align__(16) __half sB[2][BUFH];

    float acc[2][4][4] = {};
    const int m0 = blockIdx.y * 128, n0 = blockIdx.x * 128;
    hgemm512_tile(g_ao, g_wp, m0, n0, acc, sA, sB);

    const int tid = threadIdx.x, lane = tid & 31, wid = tid >> 5;
    const int g = lane >> 2, t = lane & 3;
    const int wm = (wid & 3) * 32, wn = (wid >> 2) * 32;

    #pragma unroll
    for (int i = 0; i < 2; ++i) {
        #pragma unroll
        for (int h = 0; h < 2; ++h) {
            const int m = m0 + wm + i * 16 + h * 8 + g;
            const int win = m / NTOK, tok = m % NTOK;
            const int b = win >> 4, yw = (win >> 2) & 3, xw = win & 3;
            const int y = yw * 12 + tok / 12;
            const int x = xw * 12 + tok % 12;
            float* orow = out + ((b * 2304 + y * 48 + x) << 9);
            #pragma unroll
            for (int j = 0; j < 4; ++j) {
                const int n = n0 + wn + j * 8 + 2 * t;
                float2 v;
                v.x = acc[i][j][h * 2 + 0] + bias[n + 0];
                v.y = acc[i][j][h * 2 + 1] + bias[n + 1];
                *(float2*)&orow[n] = v;
            }
        }
    }
}

// ---------------------------------------------------------------------------
extern "C" void kernel_launch(void* const* d_in, const int* in_sizes, int n_in,
                              void* d_out, int out_size)
{
    const float* hidden = (const float*)d_in[0];
    const float* qkv_w  = (const float*)d_in[1];
    const float* qkv_b  = (const float*)d_in[2];
    const float* proj_w = (const float*)d_in[3];
    const float* proj_b = (const float*)d_in[4];
    float* out = (float*)d_out;

    convert_all_kernel<<<NXB + NWB, 256>>>(hidden, qkv_w, proj_w);

    qkv_hgemm_kernel<<<dim3(NQKV / 128, MTOT / 128), 512>>>(qkv_b);

    attn_mma_kernel<<<NWIN * NHEAD, 96>>>();

    proj_hgemm_kernel<<<dim3(DIM / 128, MTOT / 128), 512>>>(proj_b, out);
}